// round 15
// baseline (speedup 1.0000x reference)
#include <cuda_runtime.h>
#include <cuda_bf16.h>
#include <math.h>
#include <cstdint>

// ---------------------------------------------------------------------------
// GGNN layer, GB300. Split-bf16 HMMA GEMMs + PERSISTENT (112-CTA) atomic
// scatter forked onto a second stream so it truly co-resides with the mh
// GEMM chain (scatter CTAs use no smem and few regs -> SM slots for both).
// Refold: mx_core = (S·X)@(Wm@gk) + b0 ; deg·(bm@gk) applied in k_gru.
//   mh = X@grk + b1 ; out = z*X + (1-z)*tanh(xh + r*rh)
// Precision: A=Ah+Al, B=Bh+Bl (bf16); D = AhBh + AlBh + AhBl (fp32 acc)
// ---------------------------------------------------------------------------

#define D_DIM 128
#define MAXN  50048            // 391*128 tile padding
#define MBTOT (MAXN / 16)      // 3128
#define SCTAS 112              // persistent scatter CTAs

__device__ float g_Wmg[D_DIM * 384];             // (W1@W2)@gk
__device__ float g_bmg[384];                     // (b1@W2+b2)@gk
__device__ float g_agg[MAXN * D_DIM];            // S·X (zero-padded)
__device__ int   g_cnt[MAXN];                    // degree
__device__ float g_mx[MAXN * 3 * D_DIM];
__device__ float g_mh[MAXN * 3 * D_DIM];
// A operands in mma-fragment order: [mb][ks][lane] -> {hi uint4, lo uint4}
__device__ uint4 g_XF[MBTOT * 8 * 32 * 2];
__device__ uint4 g_GF[MBTOT * 8 * 32 * 2];
// 6 weight tiles (mh x3, mx x3) [n][k] bf16 pairs (linear rows, 256B)
__device__ __align__(16) unsigned int g_BhW[6 * 8192];
__device__ __align__(16) unsigned int g_BlW[6 * 8192];
__device__ float g_biasAll[6 * 128];

// ---------------------------------------------------------------------------
__device__ __forceinline__ uint32_t smem_u32(const void* p) {
    uint32_t a;
    asm("{ .reg .u64 t; cvta.to.shared.u64 t, %1; cvt.u32.u64 %0, t; }"
        : "=r"(a) : "l"(p));
    return a;
}
__device__ __forceinline__ void split2(float2 v, uint32_t& hp, uint32_t& lp) {
    asm("cvt.rn.bf16x2.f32 %0, %1, %2;" : "=r"(hp) : "f"(v.y), "f"(v.x));
    float h0 = __uint_as_float(hp << 16);
    float h1 = __uint_as_float(hp & 0xFFFF0000u);
    asm("cvt.rn.bf16x2.f32 %0, %1, %2;" : "=r"(lp) : "f"(v.y - h1), "f"(v.x - h0));
}
__device__ __forceinline__ void ldsm4(uint32_t& r0, uint32_t& r1, uint32_t& r2,
                                      uint32_t& r3, uint32_t addr) {
    asm volatile("ldmatrix.sync.aligned.m8n8.x4.shared.b16 {%0,%1,%2,%3}, [%4];"
                 : "=r"(r0), "=r"(r1), "=r"(r2), "=r"(r3) : "r"(addr));
}
__device__ __forceinline__ void mma16816(float* c, const uint32_t* a,
                                         const uint32_t* b) {
    asm volatile(
        "mma.sync.aligned.m16n8k16.row.col.f32.bf16.bf16.f32 "
        "{%0,%1,%2,%3}, {%4,%5,%6,%7}, {%8,%9}, {%0,%1,%2,%3};"
        : "+f"(c[0]), "+f"(c[1]), "+f"(c[2]), "+f"(c[3])
        : "r"(a[0]), "r"(a[1]), "r"(a[2]), "r"(a[3]), "r"(b[0]), "r"(b[1]));
}
__device__ __forceinline__ void cpa16(uint32_t dst, const void* src) {
    asm volatile("cp.async.cg.shared.global [%0], [%1], 16;"
                 :: "r"(dst), "l"(src));
}
__device__ __forceinline__ void redv4(float* p, float4 v) {
    asm volatile("red.global.add.v4.f32 [%0], {%1,%2,%3,%4};"
                 :: "l"(p), "f"(v.x), "f"(v.y), "f"(v.z), "f"(v.w) : "memory");
}

// ---------------------------------------------------------------------------
// weight folding:  Wmg = (W1@W2)@gk,  bmg = (b1@W2+b2)@gk
// ---------------------------------------------------------------------------
__global__ void __launch_bounds__(384) k_foldA(const float* __restrict__ W1,
                                               const float* __restrict__ W2,
                                               const float* __restrict__ gk) {
    __shared__ float w1r[128], wmr[128];
    int i = blockIdx.x, t = threadIdx.x;
    if (t < 128) w1r[t] = W1[i * 128 + t];
    __syncthreads();
    if (t < 128) {
        float s = 0.f;
#pragma unroll 8
        for (int k = 0; k < 128; k++) s += w1r[k] * W2[k * 128 + t];
        wmr[t] = s;
    }
    __syncthreads();
    float s = 0.f;
#pragma unroll 8
    for (int k = 0; k < 128; k++) s += wmr[k] * gk[k * 384 + t];
    g_Wmg[i * 384 + t] = s;
}

__global__ void __launch_bounds__(384) k_foldB(const float* __restrict__ b1,
                                               const float* __restrict__ W2,
                                               const float* __restrict__ b2,
                                               const float* __restrict__ gk) {
    __shared__ float bmr[128];
    int t = threadIdx.x;
    if (t < 128) {
        float s = b2[t];
        for (int k = 0; k < 128; k++) s += b1[k] * W2[k * 128 + t];
        bmr[t] = s;
    }
    __syncthreads();
    float s = 0.f;
#pragma unroll 8
    for (int k = 0; k < 128; k++) s += bmr[k] * gk[k * 384 + t];
    g_bmg[t] = s;
}

// split weight tiles [n][k] (hi/lo) + biases. j<3: grk (mh); j>=3: Wmg (mx).
__global__ void __launch_bounds__(256)
k_prepW(const float* __restrict__ grk, const float* __restrict__ gb) {
    int j = blockIdx.x, tid = threadIdx.x;
    int n = tid & 127, half = tid >> 7;
    const float* src = (j < 3) ? grk : g_Wmg;
    int c0 = (j % 3) * 128;
    const float* bsrc = gb + ((j < 3) ? 384 : 0) + c0;
    unsigned int* bh = g_BhW + (size_t)j * 8192 + n * 64;
    unsigned int* bl = g_BlW + (size_t)j * 8192 + n * 64;
    for (int k = half * 64; k < half * 64 + 64; k += 2) {
        float2 v = make_float2(src[(size_t)k * 384 + c0 + n],
                               src[(size_t)(k + 1) * 384 + c0 + n]);
        uint32_t hp, lp; split2(v, hp, lp);
        bh[k >> 1] = hp;
        bl[k >> 1] = lp;
    }
    if (half == 0) g_biasAll[j * 128 + n] = bsrc[n];
}

// ---------------------------------------------------------------------------
// zero agg + degree counters
// ---------------------------------------------------------------------------
__global__ void k_zero(int n4) {
    int i = blockIdx.x * blockDim.x + threadIdx.x;
    if (i < n4) ((float4*)g_agg)[i] = make_float4(0.f, 0.f, 0.f, 0.f);
    if (i < MAXN) g_cnt[i] = 0;
}

// degree histogram (int atomics, spread addresses — cheap)
__global__ void k_hist(const int* __restrict__ ra, const int* __restrict__ rb,
                       int E) {
    int e = blockIdx.x * blockDim.x + threadIdx.x;
    if (e >= E) return;
    atomicAdd(&g_cnt[ra[e]], 1);
    atomicAdd(&g_cnt[rb[e]], 1);
}

// ---------------------------------------------------------------------------
// PERSISTENT undirected scatter-add of X rows. 112 CTAs x 8 warps; each warp
// processes 4 CONTIGUOUS edges per iteration (one int4 index load per side,
// 8 independent row LDG.128s batched ahead of 8 reds) -> ~5 edges/cyc issue,
// clamped by the LTS/atomic cap. No smem, low regs -> co-resides with GEMMs.
// ---------------------------------------------------------------------------
__global__ void __launch_bounds__(256)
k_scatterP(const float* __restrict__ X, const int* __restrict__ ra,
           const int* __restrict__ rb, int E) {
    const int w     = (blockIdx.x << 3) + (threadIdx.x >> 5);   // global warp
    const int lane  = threadIdx.x & 31;
    const int W     = gridDim.x << 3;                           // total warps
    const int Equad = E & ~3;

    for (int e = w * 4; e < Equad; e += W * 4) {
        int4 a4 = __ldg((const int4*)(ra + e));
        int4 b4 = __ldg((const int4*)(rb + e));
        float4 va0 = ((const float4*)(X + (size_t)a4.x * 128))[lane];
        float4 va1 = ((const float4*)(X + (size_t)a4.y * 128))[lane];
        float4 va2 = ((const float4*)(X + (size_t)a4.z * 128))[lane];
        float4 va3 = ((const float4*)(X + (size_t)a4.w * 128))[lane];
        float4 vb0 = ((const float4*)(X + (size_t)b4.x * 128))[lane];
        float4 vb1 = ((const float4*)(X + (size_t)b4.y * 128))[lane];
        float4 vb2 = ((const float4*)(X + (size_t)b4.z * 128))[lane];
        float4 vb3 = ((const float4*)(X + (size_t)b4.w * 128))[lane];
        redv4(g_agg + (size_t)b4.x * 128 + lane * 4, va0);
        redv4(g_agg + (size_t)b4.y * 128 + lane * 4, va1);
        redv4(g_agg + (size_t)b4.z * 128 + lane * 4, va2);
        redv4(g_agg + (size_t)b4.w * 128 + lane * 4, va3);
        redv4(g_agg + (size_t)a4.x * 128 + lane * 4, vb0);
        redv4(g_agg + (size_t)a4.y * 128 + lane * 4, vb1);
        redv4(g_agg + (size_t)a4.z * 128 + lane * 4, vb2);
        redv4(g_agg + (size_t)a4.w * 128 + lane * 4, vb3);
    }
    // tail (<4 edges), warp 0 of block 0
    if (blockIdx.x == 0 && (threadIdx.x >> 5) == 0) {
        for (int e = Equad; e < E; e++) {
            int a = __ldg(ra + e), b = __ldg(rb + e);
            float4 va = ((const float4*)(X + (size_t)a * 128))[lane];
            float4 vb = ((const float4*)(X + (size_t)b * 128))[lane];
            redv4(g_agg + (size_t)b * 128 + lane * 4, va);
            redv4(g_agg + (size_t)a * 128 + lane * 4, vb);
        }
    }
}

// ---------------------------------------------------------------------------
// split X into fragment-major hi/lo (g_XF)
// ---------------------------------------------------------------------------
__global__ void __launch_bounds__(256)
k_split(const float* __restrict__ X, int N) {
    int mb = blockIdx.x;
    int ks = threadIdx.x >> 5, lane = threadIdx.x & 31;
    int r0 = mb * 16 + (lane >> 2), r1 = r0 + 8;
    int k0 = ks * 16 + (lane & 3) * 2;
    float2 z2 = make_float2(0.f, 0.f);
    float2 v00 = (r0 < N) ? *(const float2*)(X + (size_t)r0 * 128 + k0)     : z2;
    float2 v01 = (r0 < N) ? *(const float2*)(X + (size_t)r0 * 128 + k0 + 8) : z2;
    float2 v10 = (r1 < N) ? *(const float2*)(X + (size_t)r1 * 128 + k0)     : z2;
    float2 v11 = (r1 < N) ? *(const float2*)(X + (size_t)r1 * 128 + k0 + 8) : z2;
    uint32_t h0, l0, h1, l1, h2, l2, h3, l3;
    split2(v00, h0, l0);
    split2(v10, h1, l1);
    split2(v01, h2, l2);
    split2(v11, h3, l3);
    size_t f = ((size_t)(mb * 8 + ks) * 32 + lane) * 2;
    g_XF[f]     = make_uint4(h0, h1, h2, h3);
    g_XF[f + 1] = make_uint4(l0, l1, l2, l3);
}

// split agg into fragment-major hi/lo (g_GF); agg zero-padded, no guards
__global__ void __launch_bounds__(256)
k_splitAgg(int N) {
    int mb = blockIdx.x;
    int ks = threadIdx.x >> 5, lane = threadIdx.x & 31;
    int r0 = mb * 16 + (lane >> 2), r1 = r0 + 8;
    int k0 = ks * 16 + (lane & 3) * 2;
    const float* A = g_agg;
    float2 v00 = *(const float2*)(A + (size_t)r0 * 128 + k0);
    float2 v01 = *(const float2*)(A + (size_t)r0 * 128 + k0 + 8);
    float2 v10 = *(const float2*)(A + (size_t)r1 * 128 + k0);
    float2 v11 = *(const float2*)(A + (size_t)r1 * 128 + k0 + 8);
    uint32_t h0, l0, h1, l1, h2, l2, h3, l3;
    split2(v00, h0, l0);
    split2(v10, h1, l1);
    split2(v01, h2, l2);
    split2(v11, h3, l3);
    size_t f = ((size_t)(mb * 8 + ks) * 32 + lane) * 2;
    g_GF[f]     = make_uint4(h0, h1, h2, h3);
    g_GF[f + 1] = make_uint4(l0, l1, l2, l3);
}

// ---------------------------------------------------------------------------
// persistent split-bf16 HMMA GEMM (R6-proven; barrier-free inner loop,
// B tile loaded once). j = jbase + blockIdx.y; A = XF (mh) or GF (mx).
// ---------------------------------------------------------------------------
#define SM_TOTAL 65536

__global__ void __launch_bounds__(256, 2)
k_mmagemm(int useGF, int jbase, int mtiles) {
    extern __shared__ char smem[];
    const uint32_t sb = smem_u32(smem);
    const int tid = threadIdx.x, wid = tid >> 5, lane = tid & 31;
    const int j = jbase + blockIdx.y;

    {   // load B tile once
        int r = tid >> 1, h = tid & 1;
        const char* s = (const char*)(h ? g_BlW : g_BhW)
                        + (size_t)j * 32768 + (size_t)r * 256;
        uint32_t drow = sb + h * 32768 + r * 256;
        uint32_t rx = (uint32_t)(r & 7);
#pragma unroll
        for (int c = 0; c < 16; c++)
            cpa16(drow + (((uint32_t)c ^ rx) << 4), s + c * 16);
        asm volatile("cp.async.commit_group;" ::: "memory");
        asm volatile("cp.async.wait_group 0;" ::: "memory");
        __syncthreads();
    }

    const int warp_m = wid >> 1, warp_n = wid & 1;
    const int b_row = warp_n * 64 + (lane & 7) + ((lane >> 4) << 3);
    const uint32_t b_rx = (uint32_t)(b_row & 7);
    const int b_sel = (lane >> 3) & 1;
    const uint32_t bBaseHi = sb + b_row * 256;
    const uint32_t bBaseLo = bBaseHi + 32768;

    float* dst = (j < 3) ? g_mh : g_mx;
    const int c0 = (j % 3) * 128;
    const float* biasG = g_biasAll + j * 128;
    const int tr = lane >> 2, tc = (lane & 3) * 2;
    float bx[8], by[8];
#pragma unroll
    for (int nf = 0; nf < 8; nf++) {
        int col = warp_n * 64 + nf * 8 + tc;
        bx[nf] = biasG[col];
        by[nf] = biasG[col + 1];
    }

    const uint4* AF = useGF ? g_GF : g_XF;

    for (int mt = blockIdx.x; mt < mtiles; mt += gridDim.x) {
        float acc[2][8][4];
#pragma unroll
        for (int mf = 0; mf < 2; mf++)
#pragma unroll
            for (int nf = 0; nf < 8; nf++)
#pragma unroll
                for (int q = 0; q < 4; q++) acc[mf][nf][q] = 0.f;

        const int mbBase = mt * 8 + warp_m * 2;
        const uint4* a0 = AF + (((size_t)mbBase * 8) * 32 + lane) * 2;
        const uint4* a1 = AF + (((size_t)(mbBase + 1) * 8) * 32 + lane) * 2;

#pragma unroll
        for (int s = 0; s < 8; s++) {
            uint4 ahv0 = a0[s * 64], alv0 = a0[s * 64 + 1];
            uint4 ahv1 = a1[s * 64], alv1 = a1[s * 64 + 1];
            const uint32_t* ah0 = &ahv0.x;
            const uint32_t* al0 = &alv0.x;
            const uint32_t* ah1 = &ahv1.x;
            const uint32_t* al1 = &alv1.x;

            uint32_t bfr[16];
            uint32_t lc = (uint32_t)(2 * s + b_sel);
#pragma unroll
            for (int p = 0; p < 4; p++)
                ldsm4(bfr[p * 4], bfr[p * 4 + 1], bfr[p * 4 + 2], bfr[p * 4 + 3],
                      bBaseHi + p * 16 * 256 + ((lc ^ b_rx) << 4));
#pragma unroll
            for (int nf = 0; nf < 8; nf++) {
                const uint32_t* bs = &bfr[(nf >> 1) * 4 + (nf & 1) * 2];
                mma16816(acc[0][nf], ah0, bs);
                mma16816(acc[1][nf], ah1, bs);
                mma16816(acc[0][nf], al0, bs);
                mma16816(acc[1][nf], al1, bs);
            }
#pragma unroll
            for (int p = 0; p < 4; p++)
                ldsm4(bfr[p * 4], bfr[p * 4 + 1], bfr[p * 4 + 2], bfr[p * 4 + 3],
                      bBaseLo + p * 16 * 256 + ((lc ^ b_rx) << 4));
#pragma unroll
            for (int nf = 0; nf < 8; nf++) {
                const uint32_t* bs = &bfr[(nf >> 1) * 4 + (nf & 1) * 2];
                mma16816(acc[0][nf], ah0, bs);
                mma16816(acc[1][nf], ah1, bs);
            }
        }

        const int m0 = mt * 128;
#pragma unroll
        for (int mf = 0; mf < 2; mf++) {
            int row0 = m0 + warp_m * 32 + mf * 16 + tr;
#pragma unroll
            for (int nf = 0; nf < 8; nf++) {
                int col = warp_n * 64 + nf * 8 + tc;
                *(float2*)(dst + (size_t)row0 * 384 + c0 + col) =
                    make_float2(acc[mf][nf][0] + bx[nf], acc[mf][nf][1] + by[nf]);
                *(float2*)(dst + (size_t)(row0 + 8) * 384 + c0 + col) =
                    make_float2(acc[mf][nf][2] + bx[nf], acc[mf][nf][3] + by[nf]);
            }
        }
    }
}

// ---------------------------------------------------------------------------
// fused GRU update; applies the refold's deg*bmg correction to mx gates.
// ---------------------------------------------------------------------------
__device__ __forceinline__ float sgm(float x) { return 1.f / (1.f + expf(-x)); }

__global__ void __launch_bounds__(256) k_gru(const float* __restrict__ X,
                                             float* __restrict__ out, int n4) {
    int i = blockIdx.x * 256 + threadIdx.x;
    if (i >= n4) return;
    int node = i >> 5, c = i & 31;
    const float4* mx = (const float4*)g_mx + (size_t)node * 96;
    const float4* mh = (const float4*)g_mh + (size_t)node * 96;
    const float4* bm = (const float4*)g_bmg;
    float dg = (float)g_cnt[node];
    float4 bz = bm[c], brv = bm[32 + c], bhv = bm[64 + c];
    float4 xz = mx[c],      rz = mh[c];
    float4 xr = mx[32 + c], rr = mh[32 + c];
    float4 xh = mx[64 + c], rh = mh[64 + c];
    xz.x += dg * bz.x;  xz.y += dg * bz.y;  xz.z += dg * bz.z;  xz.w += dg * bz.w;
    xr.x += dg * brv.x; xr.y += dg * brv.y; xr.z += dg * brv.z; xr.w += dg * brv.w;
    xh.x += dg * bhv.x; xh.y += dg * bhv.y; xh.z += dg * bhv.z; xh.w += dg * bhv.w;
    float4 x = ((const float4*)X)[i];
    float4 o;
    { float z = sgm(xz.x + rz.x), r = sgm(xr.x + rr.x);
      o.x = z * x.x + (1.f - z) * tanhf(xh.x + r * rh.x); }
    { float z = sgm(xz.y + rz.y), r = sgm(xr.y + rr.y);
      o.y = z * x.y + (1.f - z) * tanhf(xh.y + r * rh.y); }
    { float z = sgm(xz.z + rz.z), r = sgm(xr.z + rr.z);
      o.z = z * x.z + (1.f - z) * tanhf(xh.z + r * rh.z); }
    { float z = sgm(xz.w + rz.w), r = sgm(xr.w + rr.w);
      o.w = z * x.w + (1.f - z) * tanhf(xh.w + r * rh.w); }
    ((float4*)out)[i] = o;
}

// ---------------------------------------------------------------------------
extern "C" void kernel_launch(void* const* d_in, const int* in_sizes, int n_in,
                              void* d_out, int out_size)
{
    const float* X   = (const float*)d_in[0];
    const int*   ra  = (const int*)  d_in[1];
    const int*   rb  = (const int*)  d_in[2];
    const float* W1  = (const float*)d_in[3];
    const float* b1  = (const float*)d_in[4];
    const float* W2  = (const float*)d_in[5];
    const float* b2  = (const float*)d_in[6];
    const float* gk  = (const float*)d_in[7];
    const float* grk = (const float*)d_in[8];
    const float* gb  = (const float*)d_in[9];

    const int N = in_sizes[0] / D_DIM;
    const int E = in_sizes[1];
    const int mtiles = (N + 127) / 128;          // 391
    const int mbtot  = mtiles * 8;               // 3128

    // one-time (first call is the uncaptured correctness pass)
    static cudaStream_t s2 = nullptr;
    static cudaEvent_t  evF = nullptr, evJ = nullptr;
    if (s2 == nullptr) {
        cudaStreamCreateWithFlags(&s2, cudaStreamNonBlocking);
        cudaEventCreateWithFlags(&evF, cudaEventDisableTiming);
        cudaEventCreateWithFlags(&evJ, cudaEventDisableTiming);
        cudaFuncSetAttribute(k_mmagemm,
                             cudaFuncAttributeMaxDynamicSharedMemorySize,
                             SM_TOTAL);
    }

    // zero first (scatter branch depends only on this)
    k_zero<<<(MAXN * 32 + 255) / 256, 256>>>(MAXN * 32);

    // fork: scatter branch on s2 (reads X directly thanks to the refold);
    // small persistent grid leaves SM slots for the GEMM chain.
    cudaEventRecord(evF, 0);
    cudaStreamWaitEvent(s2, evF, 0);
    k_hist<<<(E + 255) / 256, 256, 0, s2>>>(ra, rb, E);
    k_scatterP<<<SCTAS, 256, 0, s2>>>(X, ra, rb, E);
    cudaEventRecord(evJ, s2);

    // legacy branch, concurrent with scatter: folds + weight split + X split
    // + mh GEMM (222 CTAs = 2/SM on 111 SMs; scatter co-resides).
    k_foldA<<<128, 384>>>(W1, W2, gk);
    k_foldB<<<1, 384>>>(b1, W2, b2, gk);
    k_prepW<<<6, 256>>>(grk, gb);
    k_split<<<mbtot, 256>>>(X, N);
    k_mmagemm<<<dim3(74, 3), 256, SM_TOTAL>>>(0, 0, mtiles);

    // join: mx chain needs the completed agg
    cudaStreamWaitEvent(0, evJ, 0);

    // split agg -> GF, mx GEMM, GRU epilogue
    k_splitAgg<<<mbtot, 256>>>(N);
    k_mmagemm<<<dim3(98, 3), 256, SM_TOTAL>>>(1, 3, mtiles);
    k_gru<<<(N * 32 + 255) / 256, 256>>>(X, (float*)d_out, N * 32);
}

// round 16
// speedup vs baseline: 2.2244x; 2.2244x over previous
#include <cuda_runtime.h>
#include <cuda_bf16.h>
#include <math.h>
#include <cstdint>

// ---------------------------------------------------------------------------
// GGNN layer, GB300. Serial pipeline of proven kernels.
// Refold: mx_core = (S·X)@(Wm@gk) + b0 ; deg·(bm@gk) applied in k_gru.
//   mh = X@grk + b1 ; out = z*X + (1-z)*tanh(xh + r*rh)
// Precision: A=Ah+Al, B=Bh+Bl (bf16); D = AhBh + AlBh + AhBl (fp32 acc)
// State (agg, cnt) is zero at module load and re-zeroed by consumer kernels
// (splitAgg / gru) so each graph replay starts clean — no k_zero pass.
// ---------------------------------------------------------------------------

#define D_DIM 128
#define MAXN  50048            // 391*128 tile padding
#define MBTOT (MAXN / 16)      // 3128

__device__ float g_Wm[D_DIM * D_DIM];            // W1@W2
__device__ float g_Wmg[D_DIM * 384];             // (W1@W2)@gk
__device__ float g_bmg[384];                     // (b1@W2+b2)@gk
__device__ float g_agg[MAXN * D_DIM];            // S·X (zero between runs)
__device__ int   g_cnt[MAXN];                    // degree (zero between runs)
__device__ float g_mx[MAXN * 3 * D_DIM];
__device__ float g_mh[MAXN * 3 * D_DIM];
// A operands in mma-fragment order: [mb][ks][lane] -> {hi uint4, lo uint4}
__device__ uint4 g_XF[MBTOT * 8 * 32 * 2];
__device__ uint4 g_GF[MBTOT * 8 * 32 * 2];
// 6 weight tiles (mh x3, mx x3) [n][k] bf16 pairs (linear rows, 256B)
__device__ __align__(16) unsigned int g_BhW[6 * 8192];
__device__ __align__(16) unsigned int g_BlW[6 * 8192];
__device__ float g_biasAll[6 * 128];

// ---------------------------------------------------------------------------
__device__ __forceinline__ uint32_t smem_u32(const void* p) {
    uint32_t a;
    asm("{ .reg .u64 t; cvta.to.shared.u64 t, %1; cvt.u32.u64 %0, t; }"
        : "=r"(a) : "l"(p));
    return a;
}
__device__ __forceinline__ void split2(float2 v, uint32_t& hp, uint32_t& lp) {
    asm("cvt.rn.bf16x2.f32 %0, %1, %2;" : "=r"(hp) : "f"(v.y), "f"(v.x));
    float h0 = __uint_as_float(hp << 16);
    float h1 = __uint_as_float(hp & 0xFFFF0000u);
    asm("cvt.rn.bf16x2.f32 %0, %1, %2;" : "=r"(lp) : "f"(v.y - h1), "f"(v.x - h0));
}
__device__ __forceinline__ void ldsm4(uint32_t& r0, uint32_t& r1, uint32_t& r2,
                                      uint32_t& r3, uint32_t addr) {
    asm volatile("ldmatrix.sync.aligned.m8n8.x4.shared.b16 {%0,%1,%2,%3}, [%4];"
                 : "=r"(r0), "=r"(r1), "=r"(r2), "=r"(r3) : "r"(addr));
}
__device__ __forceinline__ void mma16816(float* c, const uint32_t* a,
                                         const uint32_t* b) {
    asm volatile(
        "mma.sync.aligned.m16n8k16.row.col.f32.bf16.bf16.f32 "
        "{%0,%1,%2,%3}, {%4,%5,%6,%7}, {%8,%9}, {%0,%1,%2,%3};"
        : "+f"(c[0]), "+f"(c[1]), "+f"(c[2]), "+f"(c[3])
        : "r"(a[0]), "r"(a[1]), "r"(a[2]), "r"(a[3]), "r"(b[0]), "r"(b[1]));
}
__device__ __forceinline__ void cpa16(uint32_t dst, const void* src) {
    asm volatile("cp.async.cg.shared.global [%0], [%1], 16;"
                 :: "r"(dst), "l"(src));
}

// ---------------------------------------------------------------------------
// fast weight folding (ILP-4, smem row cache)
// ---------------------------------------------------------------------------
__global__ void __launch_bounds__(128) k_foldWm(const float* __restrict__ W1,
                                                const float* __restrict__ W2) {
    __shared__ float row[128];
    int i = blockIdx.x, t = threadIdx.x;
    row[t] = W1[i * 128 + t];
    __syncthreads();
    float s0 = 0.f, s1 = 0.f, s2 = 0.f, s3 = 0.f;
#pragma unroll 8
    for (int k = 0; k < 128; k += 4) {
        s0 += row[k]     * W2[(k)     * 128 + t];
        s1 += row[k + 1] * W2[(k + 1) * 128 + t];
        s2 += row[k + 2] * W2[(k + 2) * 128 + t];
        s3 += row[k + 3] * W2[(k + 3) * 128 + t];
    }
    g_Wm[i * 128 + t] = (s0 + s1) + (s2 + s3);
}

__global__ void __launch_bounds__(384) k_foldWmg(const float* __restrict__ gk) {
    __shared__ float row[128];
    int i = blockIdx.x, t = threadIdx.x;
    if (t < 128) row[t] = g_Wm[i * 128 + t];
    __syncthreads();
    float s0 = 0.f, s1 = 0.f, s2 = 0.f, s3 = 0.f;
#pragma unroll 8
    for (int k = 0; k < 128; k += 4) {
        s0 += row[k]     * gk[(k)     * 384 + t];
        s1 += row[k + 1] * gk[(k + 1) * 384 + t];
        s2 += row[k + 2] * gk[(k + 2) * 384 + t];
        s3 += row[k + 3] * gk[(k + 3) * 384 + t];
    }
    g_Wmg[i * 384 + t] = (s0 + s1) + (s2 + s3);
}

__global__ void __launch_bounds__(384) k_foldB(const float* __restrict__ b1,
                                               const float* __restrict__ W2,
                                               const float* __restrict__ b2,
                                               const float* __restrict__ gk) {
    __shared__ float bmr[128];
    int t = threadIdx.x;
    if (t < 128) {
        float s0 = 0.f, s1 = 0.f, s2 = 0.f, s3 = 0.f;
#pragma unroll 8
        for (int k = 0; k < 128; k += 4) {
            s0 += b1[k]     * W2[(k)     * 128 + t];
            s1 += b1[k + 1] * W2[(k + 1) * 128 + t];
            s2 += b1[k + 2] * W2[(k + 2) * 128 + t];
            s3 += b1[k + 3] * W2[(k + 3) * 128 + t];
        }
        bmr[t] = b2[t] + (s0 + s1) + (s2 + s3);
    }
    __syncthreads();
    float s0 = 0.f, s1 = 0.f, s2 = 0.f, s3 = 0.f;
#pragma unroll 8
    for (int k = 0; k < 128; k += 4) {
        s0 += bmr[k]     * gk[(k)     * 384 + t];
        s1 += bmr[k + 1] * gk[(k + 1) * 384 + t];
        s2 += bmr[k + 2] * gk[(k + 2) * 384 + t];
        s3 += bmr[k + 3] * gk[(k + 3) * 384 + t];
    }
    g_bmg[t] = (s0 + s1) + (s2 + s3);
}

// split weight tiles [n][k] (hi/lo) + biases. j<3: grk (mh); j>=3: Wmg (mx).
__global__ void __launch_bounds__(256)
k_prepW(const float* __restrict__ grk, const float* __restrict__ gb) {
    int j = blockIdx.x, tid = threadIdx.x;
    int n = tid & 127, half = tid >> 7;
    const float* src = (j < 3) ? grk : g_Wmg;
    int c0 = (j % 3) * 128;
    const float* bsrc = gb + ((j < 3) ? 384 : 0) + c0;
    unsigned int* bh = g_BhW + (size_t)j * 8192 + n * 64;
    unsigned int* bl = g_BlW + (size_t)j * 8192 + n * 64;
    for (int k = half * 64; k < half * 64 + 64; k += 2) {
        float2 v = make_float2(src[(size_t)k * 384 + c0 + n],
                               src[(size_t)(k + 1) * 384 + c0 + n]);
        uint32_t hp, lp; split2(v, hp, lp);
        bh[k >> 1] = hp;
        bl[k >> 1] = lp;
    }
    if (half == 0) g_biasAll[j * 128 + n] = bsrc[n];
}

// ---------------------------------------------------------------------------
// degree histogram (int atomics, spread addresses; cnt zeroed by prior gru)
// ---------------------------------------------------------------------------
__global__ void k_hist(const int* __restrict__ ra, const int* __restrict__ rb,
                       int E) {
    int e = blockIdx.x * blockDim.x + threadIdx.x;
    if (e >= E) return;
    atomicAdd(&g_cnt[ra[e]], 1);
    atomicAdd(&g_cnt[rb[e]], 1);
}

// ---------------------------------------------------------------------------
// undirected scatter-add of X rows: one edge per warp, red.v4 both ways.
// (agg zeroed by prior splitAgg / module load.)
// ---------------------------------------------------------------------------
__global__ void __launch_bounds__(256)
k_scatter(const float* __restrict__ X, const int* __restrict__ ra,
          const int* __restrict__ rb, int E) {
    int w    = (blockIdx.x * 256 + threadIdx.x) >> 5;
    int lane = threadIdx.x & 31;
    if (w >= E) return;
    int a = ra[w];
    int b = rb[w];
    float4 va = ((const float4*)(X + (size_t)a * 128))[lane];
    float4 vb = ((const float4*)(X + (size_t)b * 128))[lane];
    float* pb = g_agg + (size_t)b * 128 + lane * 4;
    float* pa = g_agg + (size_t)a * 128 + lane * 4;
    asm volatile("red.global.add.v4.f32 [%0], {%1,%2,%3,%4};"
                 :: "l"(pb), "f"(va.x), "f"(va.y), "f"(va.z), "f"(va.w) : "memory");
    asm volatile("red.global.add.v4.f32 [%0], {%1,%2,%3,%4};"
                 :: "l"(pa), "f"(vb.x), "f"(vb.y), "f"(vb.z), "f"(vb.w) : "memory");
}

// ---------------------------------------------------------------------------
// split X into fragment-major hi/lo (g_XF)
// ---------------------------------------------------------------------------
__global__ void __launch_bounds__(256)
k_split(const float* __restrict__ X, int N) {
    int mb = blockIdx.x;
    int ks = threadIdx.x >> 5, lane = threadIdx.x & 31;
    int r0 = mb * 16 + (lane >> 2), r1 = r0 + 8;
    int k0 = ks * 16 + (lane & 3) * 2;
    float2 z2 = make_float2(0.f, 0.f);
    float2 v00 = (r0 < N) ? *(const float2*)(X + (size_t)r0 * 128 + k0)     : z2;
    float2 v01 = (r0 < N) ? *(const float2*)(X + (size_t)r0 * 128 + k0 + 8) : z2;
    float2 v10 = (r1 < N) ? *(const float2*)(X + (size_t)r1 * 128 + k0)     : z2;
    float2 v11 = (r1 < N) ? *(const float2*)(X + (size_t)r1 * 128 + k0 + 8) : z2;
    uint32_t h0, l0, h1, l1, h2, l2, h3, l3;
    split2(v00, h0, l0);
    split2(v10, h1, l1);
    split2(v01, h2, l2);
    split2(v11, h3, l3);
    size_t f = ((size_t)(mb * 8 + ks) * 32 + lane) * 2;
    g_XF[f]     = make_uint4(h0, h1, h2, h3);
    g_XF[f + 1] = make_uint4(l0, l1, l2, l3);
}

// split agg into fragment-major hi/lo (g_GF), then re-zero the agg words it
// read (exclusive per-thread coverage) so the next replay starts clean.
__global__ void __launch_bounds__(256)
k_splitAgg(int N) {
    int mb = blockIdx.x;
    int ks = threadIdx.x >> 5, lane = threadIdx.x & 31;
    int r0 = mb * 16 + (lane >> 2), r1 = r0 + 8;
    int k0 = ks * 16 + (lane & 3) * 2;
    float* A = g_agg;
    float2* p00 = (float2*)(A + (size_t)r0 * 128 + k0);
    float2* p01 = (float2*)(A + (size_t)r0 * 128 + k0 + 8);
    float2* p10 = (float2*)(A + (size_t)r1 * 128 + k0);
    float2* p11 = (float2*)(A + (size_t)r1 * 128 + k0 + 8);
    float2 v00 = *p00, v01 = *p01, v10 = *p10, v11 = *p11;
    uint32_t h0, l0, h1, l1, h2, l2, h3, l3;
    split2(v00, h0, l0);
    split2(v10, h1, l1);
    split2(v01, h2, l2);
    split2(v11, h3, l3);
    size_t f = ((size_t)(mb * 8 + ks) * 32 + lane) * 2;
    g_GF[f]     = make_uint4(h0, h1, h2, h3);
    g_GF[f + 1] = make_uint4(l0, l1, l2, l3);
    float2 z2 = make_float2(0.f, 0.f);
    *p00 = z2; *p01 = z2; *p10 = z2; *p11 = z2;
}

// ---------------------------------------------------------------------------
// persistent split-bf16 HMMA GEMM (R6-proven; barrier-free inner loop,
// B tile loaded once). j = jbase + blockIdx.y; A = XF (mh) or GF (mx).
// ---------------------------------------------------------------------------
#define SM_TOTAL 65536

__global__ void __launch_bounds__(256, 2)
k_mmagemm(int useGF, int jbase, int mtiles) {
    extern __shared__ char smem[];
    const uint32_t sb = smem_u32(smem);
    const int tid = threadIdx.x, wid = tid >> 5, lane = tid & 31;
    const int j = jbase + blockIdx.y;

    {   // load B tile once
        int r = tid >> 1, h = tid & 1;
        const char* s = (const char*)(h ? g_BlW : g_BhW)
                        + (size_t)j * 32768 + (size_t)r * 256;
        uint32_t drow = sb + h * 32768 + r * 256;
        uint32_t rx = (uint32_t)(r & 7);
#pragma unroll
        for (int c = 0; c < 16; c++)
            cpa16(drow + (((uint32_t)c ^ rx) << 4), s + c * 16);
        asm volatile("cp.async.commit_group;" ::: "memory");
        asm volatile("cp.async.wait_group 0;" ::: "memory");
        __syncthreads();
    }

    const int warp_m = wid >> 1, warp_n = wid & 1;
    const int b_row = warp_n * 64 + (lane & 7) + ((lane >> 4) << 3);
    const uint32_t b_rx = (uint32_t)(b_row & 7);
    const int b_sel = (lane >> 3) & 1;
    const uint32_t bBaseHi = sb + b_row * 256;
    const uint32_t bBaseLo = bBaseHi + 32768;

    float* dst = (j < 3) ? g_mh : g_mx;
    const int c0 = (j % 3) * 128;
    const float* biasG = g_biasAll + j * 128;
    const int tr = lane >> 2, tc = (lane & 3) * 2;
    float bx[8], by[8];
#pragma unroll
    for (int nf = 0; nf < 8; nf++) {
        int col = warp_n * 64 + nf * 8 + tc;
        bx[nf] = biasG[col];
        by[nf] = biasG[col + 1];
    }

    const uint4* AF = useGF ? g_GF : g_XF;

    for (int mt = blockIdx.x; mt < mtiles; mt += gridDim.x) {
        float acc[2][8][4];
#pragma unroll
        for (int mf = 0; mf < 2; mf++)
#pragma unroll
            for (int nf = 0; nf < 8; nf++)
#pragma unroll
                for (int q = 0; q < 4; q++) acc[mf][nf][q] = 0.f;

        const int mbBase = mt * 8 + warp_m * 2;
        const uint4* a0 = AF + (((size_t)mbBase * 8) * 32 + lane) * 2;
        const uint4* a1 = AF + (((size_t)(mbBase + 1) * 8) * 32 + lane) * 2;

#pragma unroll
        for (int s = 0; s < 8; s++) {
            uint4 ahv0 = a0[s * 64], alv0 = a0[s * 64 + 1];
            uint4 ahv1 = a1[s * 64], alv1 = a1[s * 64 + 1];
            const uint32_t* ah0 = &ahv0.x;
            const uint32_t* al0 = &alv0.x;
            const uint32_t* ah1 = &ahv1.x;
            const uint32_t* al1 = &alv1.x;

            uint32_t bfr[16];
            uint32_t lc = (uint32_t)(2 * s + b_sel);
#pragma unroll
            for (int p = 0; p < 4; p++)
                ldsm4(bfr[p * 4], bfr[p * 4 + 1], bfr[p * 4 + 2], bfr[p * 4 + 3],
                      bBaseHi + p * 16 * 256 + ((lc ^ b_rx) << 4));
#pragma unroll
            for (int nf = 0; nf < 8; nf++) {
                const uint32_t* bs = &bfr[(nf >> 1) * 4 + (nf & 1) * 2];
                mma16816(acc[0][nf], ah0, bs);
                mma16816(acc[1][nf], ah1, bs);
                mma16816(acc[0][nf], al0, bs);
                mma16816(acc[1][nf], al1, bs);
            }
#pragma unroll
            for (int p = 0; p < 4; p++)
                ldsm4(bfr[p * 4], bfr[p * 4 + 1], bfr[p * 4 + 2], bfr[p * 4 + 3],
                      bBaseLo + p * 16 * 256 + ((lc ^ b_rx) << 4));
#pragma unroll
            for (int nf = 0; nf < 8; nf++) {
                const uint32_t* bs = &bfr[(nf >> 1) * 4 + (nf & 1) * 2];
                mma16816(acc[0][nf], ah0, bs);
                mma16816(acc[1][nf], ah1, bs);
            }
        }

        const int m0 = mt * 128;
#pragma unroll
        for (int mf = 0; mf < 2; mf++) {
            int row0 = m0 + warp_m * 32 + mf * 16 + tr;
#pragma unroll
            for (int nf = 0; nf < 8; nf++) {
                int col = warp_n * 64 + nf * 8 + tc;
                *(float2*)(dst + (size_t)row0 * 384 + c0 + col) =
                    make_float2(acc[mf][nf][0] + bx[nf], acc[mf][nf][1] + by[nf]);
                *(float2*)(dst + (size_t)(row0 + 8) * 384 + c0 + col) =
                    make_float2(acc[mf][nf][2] + bx[nf], acc[mf][nf][3] + by[nf]);
            }
        }
    }
}

// ---------------------------------------------------------------------------
// fused GRU update; applies deg*bmg refold correction, then re-zeroes cnt
// for the next replay (warp-lockstep: reads precede the lane-0 store).
// ---------------------------------------------------------------------------
__device__ __forceinline__ float sgm(float x) { return 1.f / (1.f + expf(-x)); }

__global__ void __launch_bounds__(256) k_gru(const float* __restrict__ X,
                                             float* __restrict__ out, int n4) {
    int i = blockIdx.x * 256 + threadIdx.x;
    if (i >= n4) return;
    int node = i >> 5, c = i & 31;
    const float4* mx = (const float4*)g_mx + (size_t)node * 96;
    const float4* mh = (const float4*)g_mh + (size_t)node * 96;
    const float4* bm = (const float4*)g_bmg;
    float dg = (float)g_cnt[node];
    if (c == 0) g_cnt[node] = 0;
    float4 bz = bm[c], brv = bm[32 + c], bhv = bm[64 + c];
    float4 xz = mx[c],      rz = mh[c];
    float4 xr = mx[32 + c], rr = mh[32 + c];
    float4 xh = mx[64 + c], rh = mh[64 + c];
    xz.x += dg * bz.x;  xz.y += dg * bz.y;  xz.z += dg * bz.z;  xz.w += dg * bz.w;
    xr.x += dg * brv.x; xr.y += dg * brv.y; xr.z += dg * brv.z; xr.w += dg * brv.w;
    xh.x += dg * bhv.x; xh.y += dg * bhv.y; xh.z += dg * bhv.z; xh.w += dg * bhv.w;
    float4 x = ((const float4*)X)[i];
    float4 o;
    { float z = sgm(xz.x + rz.x), r = sgm(xr.x + rr.x);
      o.x = z * x.x + (1.f - z) * tanhf(xh.x + r * rh.x); }
    { float z = sgm(xz.y + rz.y), r = sgm(xr.y + rr.y);
      o.y = z * x.y + (1.f - z) * tanhf(xh.y + r * rh.y); }
    { float z = sgm(xz.z + rz.z), r = sgm(xr.z + rr.z);
      o.z = z * x.z + (1.f - z) * tanhf(xh.z + r * rh.z); }
    { float z = sgm(xz.w + rz.w), r = sgm(xr.w + rr.w);
      o.w = z * x.w + (1.f - z) * tanhf(xh.w + r * rh.w); }
    ((float4*)out)[i] = o;
}

// ---------------------------------------------------------------------------
extern "C" void kernel_launch(void* const* d_in, const int* in_sizes, int n_in,
                              void* d_out, int out_size)
{
    const float* X   = (const float*)d_in[0];
    const int*   ra  = (const int*)  d_in[1];
    const int*   rb  = (const int*)  d_in[2];
    const float* W1  = (const float*)d_in[3];
    const float* b1  = (const float*)d_in[4];
    const float* W2  = (const float*)d_in[5];
    const float* b2  = (const float*)d_in[6];
    const float* gk  = (const float*)d_in[7];
    const float* grk = (const float*)d_in[8];
    const float* gb  = (const float*)d_in[9];

    const int N = in_sizes[0] / D_DIM;
    const int E = in_sizes[1];
    const int mtiles = (N + 127) / 128;          // 391
    const int mbtot  = mtiles * 8;               // 3128

    cudaFuncSetAttribute(k_mmagemm, cudaFuncAttributeMaxDynamicSharedMemorySize,
                         SM_TOTAL);

    // 1-2: degree histogram + heavy scatter (agg/cnt already zero)
    k_hist<<<(E + 255) / 256, 256>>>(ra, rb, E);
    k_scatter<<<(E + 7) / 8, 256>>>(X, ra, rb, E);

    // 3-6: fast weight folding + split weight tiles
    k_foldWm<<<128, 128>>>(W1, W2);
    k_foldWmg<<<128, 384>>>(gk);
    k_foldB<<<1, 384>>>(b1, W2, b2, gk);
    k_prepW<<<6, 256>>>(grk, gb);

    // 7-8: split X, mh GEMM (A = XF)
    k_split<<<mbtot, 256>>>(X, N);
    k_mmagemm<<<dim3(98, 3), 256, SM_TOTAL>>>(0, 0, mtiles);

    // 9-10: split agg (+re-zero agg), mx GEMM (A = GF)
    k_splitAgg<<<mbtot, 256>>>(N);
    k_mmagemm<<<dim3(98, 3), 256, SM_TOTAL>>>(1, 3, mtiles);

    // 11: GRU epilogue (+deg*bmg, re-zero cnt)
    k_gru<<<(N * 32 + 255) / 256, 256>>>(X, (float*)d_out, N * 32);
}

// round 17
// speedup vs baseline: 2.7503x; 1.2364x over previous
#include <cuda_runtime.h>
#include <cuda_bf16.h>
#include <math.h>
#include <cstdint>

// ---------------------------------------------------------------------------
// GGNN layer, GB300. R6-champion pipeline (split-bf16 HMMA GEMMs, fragment-
// major A, one-edge-per-warp atomic scatter of msg) + ILP-4 folds and
// MUFU-based GRU epilogue.
//   msg = X @ (W1@W2) + (b1@W2+b2); agg = undirected scatter-add of msg;
//   mh = X@grk + b1 ; mx = agg@gk + b0 ; out = z*X + (1-z)*tanh(xh + r*rh)
// Precision: A=Ah+Al, B=Bh+Bl (bf16); D = AhBh + AlBh + AhBl (fp32 acc)
// ---------------------------------------------------------------------------

#define D_DIM 128
#define MAXN  50048            // 391*128 — exact tile padding
#define MBTOT (MAXN / 16)      // 3128

__device__ float g_Wm[D_DIM * D_DIM];            // W1@W2
__device__ float g_bm[D_DIM];                    // b1@W2 + b2
__device__ float g_msg[MAXN * D_DIM];
__device__ float g_agg[MAXN * D_DIM];
__device__ float g_mx[MAXN * 3 * D_DIM];
__device__ float g_mh[MAXN * 3 * D_DIM];
// A operands in mma-fragment order: [mb][ks][lane] -> {hi uint4, lo uint4}
__device__ uint4 g_XF[MBTOT * 8 * 32 * 2];
__device__ uint4 g_GF[MBTOT * 8 * 32 * 2];
// 7 weight tiles (msg, mh x3, mx x3) [n][k] bf16 pairs (linear rows, 256B)
__device__ __align__(16) unsigned int g_BhW[7 * 8192];
__device__ __align__(16) unsigned int g_BlW[7 * 8192];
__device__ float g_biasAll[7 * 128];

// ---------------------------------------------------------------------------
__device__ __forceinline__ uint32_t smem_u32(const void* p) {
    uint32_t a;
    asm("{ .reg .u64 t; cvta.to.shared.u64 t, %1; cvt.u32.u64 %0, t; }"
        : "=r"(a) : "l"(p));
    return a;
}
__device__ __forceinline__ void split2(float2 v, uint32_t& hp, uint32_t& lp) {
    asm("cvt.rn.bf16x2.f32 %0, %1, %2;" : "=r"(hp) : "f"(v.y), "f"(v.x));
    float h0 = __uint_as_float(hp << 16);
    float h1 = __uint_as_float(hp & 0xFFFF0000u);
    asm("cvt.rn.bf16x2.f32 %0, %1, %2;" : "=r"(lp) : "f"(v.y - h1), "f"(v.x - h0));
}
__device__ __forceinline__ void ldsm4(uint32_t& r0, uint32_t& r1, uint32_t& r2,
                                      uint32_t& r3, uint32_t addr) {
    asm volatile("ldmatrix.sync.aligned.m8n8.x4.shared.b16 {%0,%1,%2,%3}, [%4];"
                 : "=r"(r0), "=r"(r1), "=r"(r2), "=r"(r3) : "r"(addr));
}
__device__ __forceinline__ void mma16816(float* c, const uint32_t* a,
                                         const uint32_t* b) {
    asm volatile(
        "mma.sync.aligned.m16n8k16.row.col.f32.bf16.bf16.f32 "
        "{%0,%1,%2,%3}, {%4,%5,%6,%7}, {%8,%9}, {%0,%1,%2,%3};"
        : "+f"(c[0]), "+f"(c[1]), "+f"(c[2]), "+f"(c[3])
        : "r"(a[0]), "r"(a[1]), "r"(a[2]), "r"(a[3]), "r"(b[0]), "r"(b[1]));
}
__device__ __forceinline__ void cpa16(uint32_t dst, const void* src) {
    asm volatile("cp.async.cg.shared.global [%0], [%1], 16;"
                 :: "r"(dst), "l"(src));
}

// ---------------------------------------------------------------------------
// weight prep (ILP-4: 4 independent partial sums break the FMA chain)
// ---------------------------------------------------------------------------
__global__ void __launch_bounds__(128) k_fold_w(const float* __restrict__ W1,
                                                const float* __restrict__ W2) {
    __shared__ float row[128];
    int i = blockIdx.x, n = threadIdx.x;
    row[n] = W1[i * 128 + n];
    __syncthreads();
    float s0 = 0.f, s1 = 0.f, s2 = 0.f, s3 = 0.f;
#pragma unroll 8
    for (int k = 0; k < 128; k += 4) {
        s0 += row[k]     * W2[(k)     * 128 + n];
        s1 += row[k + 1] * W2[(k + 1) * 128 + n];
        s2 += row[k + 2] * W2[(k + 2) * 128 + n];
        s3 += row[k + 3] * W2[(k + 3) * 128 + n];
    }
    g_Wm[i * 128 + n] = (s0 + s1) + (s2 + s3);
}

__global__ void k_fold_b(const float* __restrict__ b1,
                         const float* __restrict__ W2,
                         const float* __restrict__ b2) {
    int n = threadIdx.x;
    float s0 = 0.f, s1 = 0.f, s2 = 0.f, s3 = 0.f;
#pragma unroll 8
    for (int k = 0; k < 128; k += 4) {
        s0 += b1[k]     * W2[(k)     * 128 + n];
        s1 += b1[k + 1] * W2[(k + 1) * 128 + n];
        s2 += b1[k + 2] * W2[(k + 2) * 128 + n];
        s3 += b1[k + 3] * W2[(k + 3) * 128 + n];
    }
    g_bm[n] = b2[n] + (s0 + s1) + (s2 + s3);
}

// build split bf16 weight tiles [n][k] + biases. 7 blocks x 256 threads.
__global__ void __launch_bounds__(256)
k_prepW(const float* __restrict__ gk, const float* __restrict__ grk,
        const float* __restrict__ gb) {
    int j = blockIdx.x, tid = threadIdx.x;
    int n = tid & 127, half = tid >> 7;
    const float* src; int NCw, c0; const float* bsrc;
    if (j == 0)      { src = g_Wm; NCw = 128; c0 = 0;             bsrc = g_bm; }
    else if (j < 4)  { src = grk;  NCw = 384; c0 = (j - 1) * 128; bsrc = gb + 384 + c0; }
    else             { src = gk;   NCw = 384; c0 = (j - 4) * 128; bsrc = gb + c0; }
    unsigned int* bh = g_BhW + (size_t)j * 8192 + n * 64;
    unsigned int* bl = g_BlW + (size_t)j * 8192 + n * 64;
    for (int k = half * 64; k < half * 64 + 64; k += 2) {
        float2 v = make_float2(src[(size_t)k * NCw + c0 + n],
                               src[(size_t)(k + 1) * NCw + c0 + n]);
        uint32_t hp, lp; split2(v, hp, lp);
        bh[k >> 1] = hp;
        bl[k >> 1] = lp;
    }
    if (half == 0) g_biasAll[j * 128 + n] = bsrc[n];
}

// ---------------------------------------------------------------------------
// zero agg
// ---------------------------------------------------------------------------
__global__ void k_zero(int n4) {
    int i = blockIdx.x * blockDim.x + threadIdx.x;
    if (i < n4) ((float4*)g_agg)[i] = make_float4(0.f, 0.f, 0.f, 0.f);
}

// ---------------------------------------------------------------------------
// split X into fragment-major hi/lo (g_XF)
// ---------------------------------------------------------------------------
__global__ void __launch_bounds__(256)
k_split(const float* __restrict__ X, int N) {
    int mb = blockIdx.x;
    int ks = threadIdx.x >> 5, lane = threadIdx.x & 31;
    int r0 = mb * 16 + (lane >> 2), r1 = r0 + 8;
    int k0 = ks * 16 + (lane & 3) * 2;
    float2 z2 = make_float2(0.f, 0.f);
    float2 v00 = (r0 < N) ? *(const float2*)(X + (size_t)r0 * 128 + k0)     : z2;
    float2 v01 = (r0 < N) ? *(const float2*)(X + (size_t)r0 * 128 + k0 + 8) : z2;
    float2 v10 = (r1 < N) ? *(const float2*)(X + (size_t)r1 * 128 + k0)     : z2;
    float2 v11 = (r1 < N) ? *(const float2*)(X + (size_t)r1 * 128 + k0 + 8) : z2;
    uint32_t h0, l0, h1, l1, h2, l2, h3, l3;
    split2(v00, h0, l0);
    split2(v10, h1, l1);
    split2(v01, h2, l2);
    split2(v11, h3, l3);
    size_t f = ((size_t)(mb * 8 + ks) * 32 + lane) * 2;
    g_XF[f]     = make_uint4(h0, h1, h2, h3);
    g_XF[f + 1] = make_uint4(l0, l1, l2, l3);
}

// split agg into fragment-major hi/lo (g_GF); agg is zero-padded, no guards
__global__ void __launch_bounds__(256)
k_splitAgg(int N) {
    int mb = blockIdx.x;
    int ks = threadIdx.x >> 5, lane = threadIdx.x & 31;
    int r0 = mb * 16 + (lane >> 2), r1 = r0 + 8;
    int k0 = ks * 16 + (lane & 3) * 2;
    const float* A = g_agg;
    float2 v00 = *(const float2*)(A + (size_t)r0 * 128 + k0);
    float2 v01 = *(const float2*)(A + (size_t)r0 * 128 + k0 + 8);
    float2 v10 = *(const float2*)(A + (size_t)r1 * 128 + k0);
    float2 v11 = *(const float2*)(A + (size_t)r1 * 128 + k0 + 8);
    uint32_t h0, l0, h1, l1, h2, l2, h3, l3;
    split2(v00, h0, l0);
    split2(v10, h1, l1);
    split2(v01, h2, l2);
    split2(v11, h3, l3);
    size_t f = ((size_t)(mb * 8 + ks) * 32 + lane) * 2;
    g_GF[f]     = make_uint4(h0, h1, h2, h3);
    g_GF[f + 1] = make_uint4(l0, l1, l2, l3);
}

// ---------------------------------------------------------------------------
// persistent split-bf16 HMMA GEMM. CTA loads its B tile (64KB hi+lo) once,
// then loops m-tiles barrier-free: A frags via LDG, B frags via ldsm.
// ---------------------------------------------------------------------------
#define SM_TOTAL 65536

__global__ void __launch_bounds__(256, 2)
k_mmagemm(int useGF, int jbase, int mtiles) {
    extern __shared__ char smem[];
    const uint32_t sb = smem_u32(smem);
    const int tid = threadIdx.x, wid = tid >> 5, lane = tid & 31;
    const int j = jbase + blockIdx.y;

    {   // load B tile once
        int r = tid >> 1, h = tid & 1;
        const char* s = (const char*)(h ? g_BlW : g_BhW)
                        + (size_t)j * 32768 + (size_t)r * 256;
        uint32_t drow = sb + h * 32768 + r * 256;
        uint32_t rx = (uint32_t)(r & 7);
#pragma unroll
        for (int c = 0; c < 16; c++)
            cpa16(drow + (((uint32_t)c ^ rx) << 4), s + c * 16);
        asm volatile("cp.async.commit_group;" ::: "memory");
        asm volatile("cp.async.wait_group 0;" ::: "memory");
        __syncthreads();
    }

    const int warp_m = wid >> 1, warp_n = wid & 1;
    const int b_row = warp_n * 64 + (lane & 7) + ((lane >> 4) << 3);
    const uint32_t b_rx = (uint32_t)(b_row & 7);
    const int b_sel = (lane >> 3) & 1;
    const uint32_t bBaseHi = sb + b_row * 256;
    const uint32_t bBaseLo = bBaseHi + 32768;

    float* dst; int NC, c0;
    if (j == 0)      { dst = g_msg; NC = 128; c0 = 0; }
    else if (j < 4)  { dst = g_mh;  NC = 384; c0 = (j - 1) * 128; }
    else             { dst = g_mx;  NC = 384; c0 = (j - 4) * 128; }
    const float* biasG = g_biasAll + j * 128;
    const int tr = lane >> 2, tc = (lane & 3) * 2;
    float bx[8], by[8];
#pragma unroll
    for (int nf = 0; nf < 8; nf++) {
        int col = warp_n * 64 + nf * 8 + tc;
        bx[nf] = biasG[col];
        by[nf] = biasG[col + 1];
    }

    const uint4* AF = useGF ? g_GF : g_XF;

    for (int mt = blockIdx.x; mt < mtiles; mt += gridDim.x) {
        float acc[2][8][4];
#pragma unroll
        for (int mf = 0; mf < 2; mf++)
#pragma unroll
            for (int nf = 0; nf < 8; nf++)
#pragma unroll
                for (int q = 0; q < 4; q++) acc[mf][nf][q] = 0.f;

        const int mbBase = mt * 8 + warp_m * 2;
        const uint4* a0 = AF + (((size_t)mbBase * 8) * 32 + lane) * 2;
        const uint4* a1 = AF + (((size_t)(mbBase + 1) * 8) * 32 + lane) * 2;

#pragma unroll
        for (int s = 0; s < 8; s++) {
            uint4 ahv0 = a0[s * 64], alv0 = a0[s * 64 + 1];
            uint4 ahv1 = a1[s * 64], alv1 = a1[s * 64 + 1];
            const uint32_t* ah0 = &ahv0.x;
            const uint32_t* al0 = &alv0.x;
            const uint32_t* ah1 = &ahv1.x;
            const uint32_t* al1 = &alv1.x;

            uint32_t bfr[16];
            uint32_t lc = (uint32_t)(2 * s + b_sel);
#pragma unroll
            for (int p = 0; p < 4; p++)
                ldsm4(bfr[p * 4], bfr[p * 4 + 1], bfr[p * 4 + 2], bfr[p * 4 + 3],
                      bBaseHi + p * 16 * 256 + ((lc ^ b_rx) << 4));
#pragma unroll
            for (int nf = 0; nf < 8; nf++) {
                const uint32_t* bs = &bfr[(nf >> 1) * 4 + (nf & 1) * 2];
                mma16816(acc[0][nf], ah0, bs);    // Ah*Bh
                mma16816(acc[1][nf], ah1, bs);
                mma16816(acc[0][nf], al0, bs);    // Al*Bh
                mma16816(acc[1][nf], al1, bs);
            }
#pragma unroll
            for (int p = 0; p < 4; p++)
                ldsm4(bfr[p * 4], bfr[p * 4 + 1], bfr[p * 4 + 2], bfr[p * 4 + 3],
                      bBaseLo + p * 16 * 256 + ((lc ^ b_rx) << 4));
#pragma unroll
            for (int nf = 0; nf < 8; nf++) {
                const uint32_t* bs = &bfr[(nf >> 1) * 4 + (nf & 1) * 2];
                mma16816(acc[0][nf], ah0, bs);    // Ah*Bl
                mma16816(acc[1][nf], ah1, bs);
            }
        }

        const int m0 = mt * 128;
#pragma unroll
        for (int mf = 0; mf < 2; mf++) {
            int row0 = m0 + warp_m * 32 + mf * 16 + tr;
#pragma unroll
            for (int nf = 0; nf < 8; nf++) {
                int col = warp_n * 64 + nf * 8 + tc;
                *(float2*)(dst + (size_t)row0 * NC + c0 + col) =
                    make_float2(acc[mf][nf][0] + bx[nf], acc[mf][nf][1] + by[nf]);
                *(float2*)(dst + (size_t)(row0 + 8) * NC + c0 + col) =
                    make_float2(acc[mf][nf][2] + bx[nf], acc[mf][nf][3] + by[nf]);
            }
        }
    }
}

// ---------------------------------------------------------------------------
// undirected scatter-add over edges: one warp per edge, red.v4 both ways.
// Reads g_msg (L2-hot: written by the GEMM immediately before).
// ---------------------------------------------------------------------------
__global__ void __launch_bounds__(256) k_scatter(const int* __restrict__ ra,
                                                 const int* __restrict__ rb, int E) {
    int w    = (blockIdx.x * 256 + threadIdx.x) >> 5;
    int lane = threadIdx.x & 31;
    if (w >= E) return;
    int a = ra[w];
    int b = rb[w];
    float4 va = ((const float4*)(g_msg + (size_t)a * 128))[lane];
    float4 vb = ((const float4*)(g_msg + (size_t)b * 128))[lane];
    float* pb = g_agg + (size_t)b * 128 + lane * 4;
    float* pa = g_agg + (size_t)a * 128 + lane * 4;
    asm volatile("red.global.add.v4.f32 [%0], {%1,%2,%3,%4};"
                 :: "l"(pb), "f"(va.x), "f"(va.y), "f"(va.z), "f"(va.w) : "memory");
    asm volatile("red.global.add.v4.f32 [%0], {%1,%2,%3,%4};"
                 :: "l"(pa), "f"(vb.x), "f"(vb.y), "f"(vb.z), "f"(vb.w) : "memory");
}

// ---------------------------------------------------------------------------
// fused GRU epilogue (MUFU tanh + fast exp/div; ~1e-5 abs err, 1e-3 budget)
// ---------------------------------------------------------------------------
__device__ __forceinline__ float sgm(float x) {
    return __fdividef(1.f, 1.f + __expf(-x));
}
__device__ __forceinline__ float ftanh(float x) {
    float y;
    asm("tanh.approx.f32 %0, %1;" : "=f"(y) : "f"(x));
    return y;
}

__global__ void __launch_bounds__(256) k_gru(const float* __restrict__ X,
                                             float* __restrict__ out, int n4) {
    int i = blockIdx.x * 256 + threadIdx.x;
    if (i >= n4) return;
    int node = i >> 5, c = i & 31;
    const float4* mx = (const float4*)g_mx + (size_t)node * 96;
    const float4* mh = (const float4*)g_mh + (size_t)node * 96;
    float4 xz = mx[c],      rz = mh[c];
    float4 xr = mx[32 + c], rr = mh[32 + c];
    float4 xh = mx[64 + c], rh = mh[64 + c];
    float4 x  = ((const float4*)X)[i];
    float4 o;
    { float z = sgm(xz.x + rz.x), r = sgm(xr.x + rr.x);
      o.x = z * x.x + (1.f - z) * ftanh(xh.x + r * rh.x); }
    { float z = sgm(xz.y + rz.y), r = sgm(xr.y + rr.y);
      o.y = z * x.y + (1.f - z) * ftanh(xh.y + r * rh.y); }
    { float z = sgm(xz.z + rz.z), r = sgm(xr.z + rr.z);
      o.z = z * x.z + (1.f - z) * ftanh(xh.z + r * rh.z); }
    { float z = sgm(xz.w + rz.w), r = sgm(xr.w + rr.w);
      o.w = z * x.w + (1.f - z) * ftanh(xh.w + r * rh.w); }
    ((float4*)out)[i] = o;
}

// ---------------------------------------------------------------------------
extern "C" void kernel_launch(void* const* d_in, const int* in_sizes, int n_in,
                              void* d_out, int out_size)
{
    const float* X   = (const float*)d_in[0];
    const int*   ra  = (const int*)  d_in[1];
    const int*   rb  = (const int*)  d_in[2];
    const float* W1  = (const float*)d_in[3];
    const float* b1  = (const float*)d_in[4];
    const float* W2  = (const float*)d_in[5];
    const float* b2  = (const float*)d_in[6];
    const float* gk  = (const float*)d_in[7];
    const float* grk = (const float*)d_in[8];
    const float* gb  = (const float*)d_in[9];

    const int N = in_sizes[0] / D_DIM;
    const int E = in_sizes[1];
    const int mtiles = (N + 127) / 128;          // 391
    const int mbtot  = mtiles * 8;               // 3128

    cudaFuncSetAttribute(k_mmagemm, cudaFuncAttributeMaxDynamicSharedMemorySize,
                         SM_TOTAL);

    // weight folding + splits (ILP-4 folds)
    k_fold_w<<<128, 128>>>(W1, W2);
    k_fold_b<<<1, 128>>>(b1, W2, b2);
    k_prepW<<<7, 256>>>(gk, grk, gb);
    k_zero<<<(N * 32 + 255) / 256, 256>>>(N * 32);
    k_split<<<mbtot, 256>>>(X, N);

    // msg (j=0) + mh (j=1..3): persistent, 2 CTAs/SM
    k_mmagemm<<<dim3(74, 4), 256, SM_TOTAL>>>(0, 0, mtiles);

    // scatter msg (L2-hot) + split agg
    k_scatter<<<(E + 7) / 8, 256>>>(ra, rb, E);
    k_splitAgg<<<mbtot, 256>>>(N);

    // mx (j=4..6)
    k_mmagemm<<<dim3(98, 3), 256, SM_TOTAL>>>(1, 4, mtiles);

    // fused GRU update
    k_gru<<<(N * 32 + 255) / 256, 256>>>(X, (float*)d_out, N * 32);
}